// round 8
// baseline (speedup 1.0000x reference)
#include <cuda_runtime.h>
#include <cuda_fp16.h>
#include <mma.h>
#include <cstdint>

using namespace nvcuda;

#define NN 100000
#define NE 1600000
#define DIN 128
#define DH 64
#define NB_SCAN ((NN + 1023) / 1024)   // 98

// ---------------- scratch (no allocations allowed) ----------------
__device__ float  g_dinv[NN];
__device__ int    g_cnt[NN];
__device__ int    g_rowptr[NN];
__device__ int    g_cursor[NN];
__device__ int    g_bsum[NB_SCAN];
__device__ int    g_csr_src[NE];
__device__ __half g_Xh [NN * DIN];     // X in fp16
__device__ __half g_W1h[DIN * DH];
__device__ __half g_W2h[DH * DH];
__device__ __half g_Xl_h[NN * DH];     // transformed features (becomes dinv-scaled)
__device__ __half g_Hs_h[NN * DH];     // dinv-scaled layer-1 activations

// ---------------- CSR build ----------------
__global__ void k_zero_cnt(int n) {
    int i = blockIdx.x * blockDim.x + threadIdx.x;
    if (i < n) g_cnt[i] = 0;
}

__global__ void k_hist4(const int* __restrict__ dst, int nE4) {
    int i = blockIdx.x * blockDim.x + threadIdx.x;
    if (i >= nE4) return;
    int4 d = reinterpret_cast<const int4*>(dst)[i];
    atomicAdd(&g_cnt[d.x], 1);
    atomicAdd(&g_cnt[d.y], 1);
    atomicAdd(&g_cnt[d.z], 1);
    atomicAdd(&g_cnt[d.w], 1);
}

__global__ __launch_bounds__(1024) void k_scan1(int n) {
    __shared__ int s[1024];
    int i = blockIdx.x * 1024 + threadIdx.x;
    int v = (i < n) ? g_cnt[i] : 0;
    s[threadIdx.x] = v;
    __syncthreads();
    for (int off = 1; off < 1024; off <<= 1) {
        int t = (threadIdx.x >= off) ? s[threadIdx.x - off] : 0;
        __syncthreads();
        s[threadIdx.x] += t;
        __syncthreads();
    }
    if (i < n) g_rowptr[i] = s[threadIdx.x] - v;       // exclusive
    if (threadIdx.x == 1023) g_bsum[blockIdx.x] = s[1023];
}

__global__ __launch_bounds__(128) void k_scan2(int nb) {
    __shared__ int s[128];
    int v = (threadIdx.x < nb) ? g_bsum[threadIdx.x] : 0;
    s[threadIdx.x] = v;
    __syncthreads();
    for (int off = 1; off < 128; off <<= 1) {
        int t = (threadIdx.x >= off) ? s[threadIdx.x - off] : 0;
        __syncthreads();
        s[threadIdx.x] += t;
        __syncthreads();
    }
    if (threadIdx.x < nb) g_bsum[threadIdx.x] = s[threadIdx.x] - v;  // exclusive
}

__global__ void k_scan3(int n) {
    int i = blockIdx.x * blockDim.x + threadIdx.x;
    if (i >= n) return;
    int rp = g_rowptr[i] + g_bsum[i >> 10];
    g_rowptr[i] = rp;
    g_cursor[i] = rp;
    g_dinv[i] = rsqrtf((float)g_cnt[i] + 1.0f);
}

__global__ void k_scatter4(const int* __restrict__ src, const int* __restrict__ dst, int nE4) {
    int i = blockIdx.x * blockDim.x + threadIdx.x;
    if (i >= nE4) return;
    int4 s = reinterpret_cast<const int4*>(src)[i];
    int4 d = reinterpret_cast<const int4*>(dst)[i];
    g_csr_src[atomicAdd(&g_cursor[d.x], 1)] = s.x;
    g_csr_src[atomicAdd(&g_cursor[d.y], 1)] = s.y;
    g_csr_src[atomicAdd(&g_cursor[d.z], 1)] = s.z;
    g_csr_src[atomicAdd(&g_cursor[d.w], 1)] = s.w;
}

// ---------------- conversions (X + W1 + W2, one kernel) ----------------
__global__ void k_conv(const float* __restrict__ X, const float* __restrict__ W1,
                       const float* __restrict__ W2, long nX4) {
    long i = (long)blockIdx.x * blockDim.x + threadIdx.x;
    if (i < nX4) {
        float4 v = reinterpret_cast<const float4*>(X)[i];
        __half2 h[2];
        h[0] = __floats2half2_rn(v.x, v.y);
        h[1] = __floats2half2_rn(v.z, v.w);
        reinterpret_cast<uint2*>(g_Xh)[i] = *reinterpret_cast<uint2*>(h);
    } else {
        long j = i - nX4;
        if (j < DIN * DH) g_W1h[j] = __float2half_rn(W1[j]);
        if (j < DH * DH)  g_W2h[j] = __float2half_rn(W2[j]);
    }
}

// ---------------- scale Xl by dinv (row-wise), in place ----------------
__global__ void k_scale_Xl(int n8) {
    int t = blockIdx.x * blockDim.x + threadIdx.x;
    if (t >= n8) return;
    int node = t >> 3;
    float dv = g_dinv[node];
    uint4* p = reinterpret_cast<uint4*>(g_Xl_h) + t;
    uint4 r = *p;
    __half2* h = reinterpret_cast<__half2*>(&r);
#pragma unroll
    for (int k = 0; k < 4; k++) {
        float2 v = __half22float2(h[k]);
        h[k] = __floats2half2_rn(v.x * dv, v.y * dv);
    }
    *p = r;
}

// ---------------- tensor-core GEMM: out = fp16( Ah @ Wh ), fp32 accum ----------------
template <int K>
__global__ __launch_bounds__(256) void k_gemm_tc(const __half* __restrict__ Ah,
                                                 const __half* __restrict__ Wh,
                                                 __half* __restrict__ outh, int n) {
    constexpr int KT = 64;
    constexpr int NT = K / KT;
    __shared__ __half sA[128][72];
    __shared__ __half sB[64][72];
    __shared__ float  sStage[8][16 * 20];

    const int tid = threadIdx.x;
    const int wid = tid >> 5;
    const int lane = tid & 31;
    const int node0 = blockIdx.x * 128;

    const int ar = tid >> 1;
    const int as = (tid & 1) * 32;
    const int br = tid >> 2;
    const int bs = (tid & 3) * 16;

    wmma::fragment<wmma::accumulator, 16, 16, 16, float> facc[4];
#pragma unroll
    for (int c = 0; c < 4; c++) wmma::fill_fragment(facc[c], 0.0f);

    for (int kt = 0; kt < NT; kt++) {
        {
            const int node = node0 + ar;
            uint4* dstp = reinterpret_cast<uint4*>(&sA[ar][as]);
            if (node < n) {
                const uint4* srcp = reinterpret_cast<const uint4*>(
                    Ah + (size_t)node * K + kt * KT + as);
#pragma unroll
                for (int u = 0; u < 4; u++) dstp[u] = srcp[u];
            } else {
                uint4 z = make_uint4(0, 0, 0, 0);
#pragma unroll
                for (int u = 0; u < 4; u++) dstp[u] = z;
            }
        }
        {
            const uint4* srcp = reinterpret_cast<const uint4*>(
                Wh + (size_t)(kt * KT + br) * DH + bs);
            uint4* dstp = reinterpret_cast<uint4*>(&sB[br][bs]);
            dstp[0] = srcp[0];
            dstp[1] = srcp[1];
        }
        __syncthreads();

#pragma unroll
        for (int k8 = 0; k8 < KT / 16; k8++) {
            wmma::fragment<wmma::matrix_a, 16, 16, 16, __half, wmma::row_major> fa;
            wmma::load_matrix_sync(fa, &sA[wid * 16][k8 * 16], 72);
#pragma unroll
            for (int c = 0; c < 4; c++) {
                wmma::fragment<wmma::matrix_b, 16, 16, 16, __half, wmma::row_major> fb;
                wmma::load_matrix_sync(fb, &sB[k8 * 16][c * 16], 72);
                wmma::mma_sync(facc[c], fa, fb, facc[c]);
            }
        }
        if (kt + 1 < NT) __syncthreads();
    }

    const int erow = lane >> 1;
    const int eseg = (lane & 1) * 8;
#pragma unroll
    for (int c = 0; c < 4; c++) {
        wmma::store_matrix_sync(&sStage[wid][0], facc[c], 20, wmma::mem_row_major);
        __syncwarp();
        const int node = node0 + wid * 16 + erow;
        if (node < n) {
            const float* sp = &sStage[wid][erow * 20 + eseg];
            __half2 h[4];
            h[0] = __floats2half2_rn(sp[0], sp[1]);
            h[1] = __floats2half2_rn(sp[2], sp[3]);
            h[2] = __floats2half2_rn(sp[4], sp[5]);
            h[3] = __floats2half2_rn(sp[6], sp[7]);
            *reinterpret_cast<uint4*>(outh + (size_t)node * DH + c * 16 + eseg) =
                *reinterpret_cast<uint4*>(h);
        }
        __syncwarp();
    }
}

// ---------------- CSR gather (pre-scaled fp16 rows, fp32 accumulate) ----------------
// One warp per node; 4 sub-groups of 8 lanes; each sub-group loads one source
// row per step (16B/lane). Cross-sub reduction at the end.
//   total = Xl_s[node] + sum_{s in row} Xl_s[s]      (rows already *dinv)
//   MODE 0: g_Hs_h[node] = fp16( dinv * relu(dinv*total + b1) )
//   MODE 1: out[node]    = dinv * total + b2
template <int MODE>
__global__ __launch_bounds__(256) void k_gather(const float* __restrict__ bias,
                                                float* __restrict__ outbuf, int n) {
    int gw = (blockIdx.x * blockDim.x + threadIdx.x) >> 5;
    if (gw >= n) return;
    const int lane = threadIdx.x & 31;
    const int sub  = lane >> 3;          // 0..3  (edge slot within 4-edge step)
    const int j    = lane & 7;           // 0..7  (column group: 8 halves)
    const int start = g_rowptr[gw];
    const int cnt   = g_cnt[gw];
    const float dvd = g_dinv[gw];
    const __half* XL = (MODE == 0) ? g_Xl_h : g_Xl_h;  // same buffer both layers

    float2 acc[4] = {{0.f,0.f},{0.f,0.f},{0.f,0.f},{0.f,0.f}};

    // self row: only sub-group 0 accumulates it
    if (sub == 0) {
        uint4 r = *reinterpret_cast<const uint4*>(XL + (size_t)gw * DH + j * 8);
        const __half2* h = reinterpret_cast<const __half2*>(&r);
#pragma unroll
        for (int k = 0; k < 4; k++) {
            float2 v = __half22float2(h[k]);
            acc[k].x += v.x; acc[k].y += v.y;
        }
    }

    for (int j0 = 0; j0 < cnt; j0 += 32) {
        int m = cnt - j0; if (m > 32) m = 32;
        int myidx = (lane < m) ? g_csr_src[start + j0 + lane] : 0;
        if (m == 32) {
#pragma unroll
            for (int t4 = 0; t4 < 8; t4++) {
                int s = __shfl_sync(0xffffffffu, myidx, t4 * 4 + sub);
                uint4 r = *reinterpret_cast<const uint4*>(XL + (size_t)s * DH + j * 8);
                const __half2* h = reinterpret_cast<const __half2*>(&r);
#pragma unroll
                for (int k = 0; k < 4; k++) {
                    float2 v = __half22float2(h[k]);
                    acc[k].x += v.x; acc[k].y += v.y;
                }
            }
        } else {
            int nb = (m + 3) >> 2;
            for (int t4 = 0; t4 < nb; t4++) {
                int e = t4 * 4 + sub;
                int s = __shfl_sync(0xffffffffu, myidx, e & 31);
                if (e < m) {
                    uint4 r = *reinterpret_cast<const uint4*>(XL + (size_t)s * DH + j * 8);
                    const __half2* h = reinterpret_cast<const __half2*>(&r);
#pragma unroll
                    for (int k = 0; k < 4; k++) {
                        float2 v = __half22float2(h[k]);
                        acc[k].x += v.x; acc[k].y += v.y;
                    }
                }
            }
        }
    }

    // reduce across the 4 sub-groups (lanes l, l+8, l+16, l+24)
#pragma unroll
    for (int k = 0; k < 4; k++) {
        acc[k].x += __shfl_xor_sync(0xffffffffu, acc[k].x, 8);
        acc[k].y += __shfl_xor_sync(0xffffffffu, acc[k].y, 8);
        acc[k].x += __shfl_xor_sync(0xffffffffu, acc[k].x, 16);
        acc[k].y += __shfl_xor_sync(0xffffffffu, acc[k].y, 16);
    }

    if (sub == 0) {
        float4 b0 = *reinterpret_cast<const float4*>(bias + j * 8);
        float4 b1v = *reinterpret_cast<const float4*>(bias + j * 8 + 4);
        float o[8];
        o[0] = fmaf(acc[0].x, dvd, b0.x);  o[1] = fmaf(acc[0].y, dvd, b0.y);
        o[2] = fmaf(acc[1].x, dvd, b0.z);  o[3] = fmaf(acc[1].y, dvd, b0.w);
        o[4] = fmaf(acc[2].x, dvd, b1v.x); o[5] = fmaf(acc[2].y, dvd, b1v.y);
        o[6] = fmaf(acc[3].x, dvd, b1v.z); o[7] = fmaf(acc[3].y, dvd, b1v.w);
        if (MODE == 0) {
            __half2 h[4];
#pragma unroll
            for (int k = 0; k < 4; k++)
                h[k] = __floats2half2_rn(fmaxf(o[2*k], 0.f) * dvd,
                                         fmaxf(o[2*k+1], 0.f) * dvd);
            *reinterpret_cast<uint4*>(g_Hs_h + (size_t)gw * DH + j * 8) =
                *reinterpret_cast<uint4*>(h);
        } else {
            float* dp = outbuf + (size_t)gw * DH + j * 8;
            *reinterpret_cast<float4*>(dp)     = make_float4(o[0], o[1], o[2], o[3]);
            *reinterpret_cast<float4*>(dp + 4) = make_float4(o[4], o[5], o[6], o[7]);
        }
    }
}

// ---------------- host launch ----------------
extern "C" void kernel_launch(void* const* d_in, const int* in_sizes, int n_in,
                              void* d_out, int out_size) {
    const int*   E  = nullptr;
    const float* X  = nullptr;
    const float* W1 = nullptr;
    const float* b1 = nullptr;
    const float* W2 = nullptr;
    const float* b2 = nullptr;
    long nE_total = 0;
    for (int i = 0; i < n_in; i++) {
        long sz = in_sizes[i];
        if (sz == 2L * NE)           { E = (const int*)d_in[i]; nE_total = sz / 2; }
        else if (sz == (long)NN * DIN) X  = (const float*)d_in[i];
        else if (sz == DIN * DH)       W1 = (const float*)d_in[i];
        else if (sz == DH * DH)        W2 = (const float*)d_in[i];
        else if (sz == DH)             { if (!b1) b1 = (const float*)d_in[i];
                                         else     b2 = (const float*)d_in[i]; }
    }
    const int n  = NN;
    const int nE = (int)nE_total;
    const int* src = E;          // E[0]
    const int* dst = E + nE;     // E[1]
    float* out = (float*)d_out;

    void *pXh = nullptr, *pW1h = nullptr, *pW2h = nullptr, *pXlh = nullptr, *pHsh = nullptr;
    cudaGetSymbolAddress(&pXh,  g_Xh);
    cudaGetSymbolAddress(&pW1h, g_W1h);
    cudaGetSymbolAddress(&pW2h, g_W2h);
    cudaGetSymbolAddress(&pXlh, g_Xl_h);
    cudaGetSymbolAddress(&pHsh, g_Hs_h);

    static cudaStream_t s1 = nullptr;
    static cudaEvent_t  eFork = nullptr, eDinv = nullptr, eCSR = nullptr;
    if (s1 == nullptr) {
        cudaStreamCreateWithFlags(&s1, cudaStreamNonBlocking);
        cudaEventCreateWithFlags(&eFork, cudaEventDisableTiming);
        cudaEventCreateWithFlags(&eDinv, cudaEventDisableTiming);
        cudaEventCreateWithFlags(&eCSR,  cudaEventDisableTiming);
    }

    const int T = 256;
    dim3 blkNode((n + T - 1) / T);
    dim3 blkEdge4((nE / 4 + T - 1) / T);
    dim3 blkGemm((n + 127) / 128);
    dim3 blkWarp(((long)n * 32 + T - 1) / T);
    long nX4 = (long)n * DIN / 4;
    long nConv = nX4 + DIN * DH;       // covers X (vec4) + W1 (and W2 within)
    dim3 blkConv((nConv + T - 1) / T);
    int n8 = n * 8;
    dim3 blkScale((n8 + T - 1) / T);

    // ---- fork: CSR build (+dinv) on s1 ----
    cudaEventRecord(eFork, 0);
    cudaStreamWaitEvent(s1, eFork, 0);

    k_zero_cnt<<<blkNode, T, 0, s1>>>(n);
    k_hist4<<<blkEdge4, T, 0, s1>>>(dst, nE / 4);
    k_scan1<<<NB_SCAN, 1024, 0, s1>>>(n);
    k_scan2<<<1, 128, 0, s1>>>(NB_SCAN);
    k_scan3<<<blkNode, T, 0, s1>>>(n);
    cudaEventRecord(eDinv, s1);                       // dinv ready
    k_scatter4<<<blkEdge4, T, 0, s1>>>(src, dst, nE / 4);
    cudaEventRecord(eCSR, s1);                        // full CSR ready

    // ---- main chain ----
    k_conv<<<blkConv, T>>>(X, W1, W2, nX4);
    k_gemm_tc<DIN><<<blkGemm, T>>>((const __half*)pXh, (const __half*)pW1h,
                                   (__half*)pXlh, n);
    cudaStreamWaitEvent(0, eDinv, 0);
    k_scale_Xl<<<blkScale, T>>>(n8);                  // Xl *= dinv (row-wise)
    cudaStreamWaitEvent(0, eCSR, 0);

    k_gather<0><<<blkWarp, T>>>(b1, nullptr, n);      // -> g_Hs_h (dinv-scaled H)
    k_gemm_tc<DH><<<blkGemm, T>>>((const __half*)pHsh, (const __half*)pW2h,
                                  (__half*)pXlh, n);  // output already scaled
    k_gather<1><<<blkWarp, T>>>(b2, out, n);
}